// round 1
// baseline (speedup 1.0000x reference)
#include <cuda_runtime.h>
#include <cstdint>

// Problem constants (fixed by the reference)
#define BB   8
#define KK   100000
#define CC   16
#define OO   16
#define HH   512
#define WW   512
#define NNODES (BB * KK)          // 800000
#define NPIX   (BB * HH * WW)     // 2097152
#define ALPHA_PRIOR 1.0f

// Intermediate grid, NHWC layout: [B, H, W, O] as float4 chunks (O=16 -> 4 float4 per pixel).
// 8 * 512 * 512 * 4 float4 = 8,388,608 float4 = 134 MB. __device__ global = sanctioned scratch.
__device__ float4 g_grid[(size_t)NPIX * 4];

// ---------------------------------------------------------------------------
// Kernel 1: zero the grid
// ---------------------------------------------------------------------------
__global__ void zero_kernel() {
    size_t i = (size_t)blockIdx.x * blockDim.x + threadIdx.x;
    if (i < (size_t)NPIX * 4) g_grid[i] = make_float4(0.f, 0.f, 0.f, 0.f);
}

// ---------------------------------------------------------------------------
// Kernel 2: per-node channel transform + scatter-add into NHWC grid
// One thread per node. Weights staged in shared memory.
// ---------------------------------------------------------------------------
__device__ __forceinline__ float dot16(const float* w,
                                       float4 f0, float4 f1, float4 f2, float4 f3) {
    const float4* w4 = (const float4*)w;
    float4 w0 = w4[0], w1 = w4[1], w2 = w4[2], w3 = w4[3];
    return w0.x * f0.x + w0.y * f0.y + w0.z * f0.z + w0.w * f0.w
         + w1.x * f1.x + w1.y * f1.y + w1.z * f1.z + w1.w * f1.w
         + w2.x * f2.x + w2.y * f2.y + w2.z * f2.z + w2.w * f2.w
         + w3.x * f3.x + w3.y * f3.y + w3.z * f3.z + w3.w * f3.w;
}

__global__ __launch_bounds__(256) void scatter_kernel(
    const float* __restrict__ node_feat,   // [B,K,C]
    const float* __restrict__ node_xy,     // [B,K,2]
    const int*   __restrict__ node_types,  // [B,K]
    const float* __restrict__ w_obj,       // [O,C]
    const float* __restrict__ w_prior)     // [O,C]
{
    __shared__ float sw[2][OO * CC];       // [type][o*16+c]
    int tid = threadIdx.x;
    if (tid < OO * CC) {
        sw[0][tid] = w_obj[tid];
        sw[1][tid] = ALPHA_PRIOR * w_prior[tid];
    }
    __syncthreads();

    int n = blockIdx.x * 256 + tid;
    if (n >= NNODES) return;

    // Load this node's 16 features (fully coalesced: 64B per thread, contiguous).
    const float4* f4 = (const float4*)(node_feat + (size_t)n * CC);
    float4 f0 = f4[0], f1 = f4[1], f2 = f4[2], f3 = f4[3];

    float x = node_xy[2 * n + 0];
    float y = node_xy[2 * n + 1];
    int   t = node_types[n] & 1;

    // jnp.round == round-half-to-even == rintf; clip to [0, 511]
    int ix = (int)fminf(fmaxf(rintf(x), 0.f), (float)(WW - 1));
    int iy = (int)fminf(fmaxf(rintf(y), 0.f), (float)(HH - 1));
    int b  = n / KK;

    const float* wbase = sw[t];
    size_t pix = ((size_t)b * HH + iy) * WW + ix;
    float4* dst = &g_grid[pix * 4];

    #pragma unroll
    for (int g = 0; g < 4; g++) {
        float4 v;
        v.x = dot16(wbase + (g * 4 + 0) * CC, f0, f1, f2, f3);
        v.y = dot16(wbase + (g * 4 + 1) * CC, f0, f1, f2, f3);
        v.z = dot16(wbase + (g * 4 + 2) * CC, f0, f1, f2, f3);
        v.w = dot16(wbase + (g * 4 + 3) * CC, f0, f1, f2, f3);
        asm volatile("red.global.add.v4.f32 [%0], {%1, %2, %3, %4};"
                     :: "l"(dst + g), "f"(v.x), "f"(v.y), "f"(v.z), "f"(v.w)
                     : "memory");
    }
}

// ---------------------------------------------------------------------------
// Kernel 3: depthwise 3x3 conv (SAME, zero pad) over NHWC grid,
// writing NCHW output. One thread per (b,y,x), all 16 channels.
// ---------------------------------------------------------------------------
__global__ __launch_bounds__(256) void conv_kernel(float* __restrict__ out) {
    int p = blockIdx.x * 256 + threadIdx.x;
    if (p >= NPIX) return;
    int b = p >> 18;
    int y = (p >> 9) & (HH - 1);
    int x = p & (WW - 1);

    const float kw[3][3] = {{0.075f, 0.125f, 0.075f},
                            {0.125f, 0.300f, 0.125f},
                            {0.075f, 0.125f, 0.075f}};

    float4 a0 = make_float4(0.f, 0.f, 0.f, 0.f);
    float4 a1 = a0, a2 = a0, a3 = a0;

    #pragma unroll
    for (int dy = -1; dy <= 1; dy++) {
        int yy = y + dy;
        if ((unsigned)yy >= HH) continue;
        #pragma unroll
        for (int dx = -1; dx <= 1; dx++) {
            int xx = x + dx;
            if ((unsigned)xx >= WW) continue;
            float k = kw[dy + 1][dx + 1];
            size_t pix = (((size_t)b * HH + yy) * WW + xx) * 4;
            float4 s0 = __ldg(&g_grid[pix + 0]);
            float4 s1 = __ldg(&g_grid[pix + 1]);
            float4 s2 = __ldg(&g_grid[pix + 2]);
            float4 s3 = __ldg(&g_grid[pix + 3]);
            a0.x += k * s0.x; a0.y += k * s0.y; a0.z += k * s0.z; a0.w += k * s0.w;
            a1.x += k * s1.x; a1.y += k * s1.y; a1.z += k * s1.z; a1.w += k * s1.w;
            a2.x += k * s2.x; a2.y += k * s2.y; a2.z += k * s2.z; a2.w += k * s2.w;
            a3.x += k * s3.x; a3.y += k * s3.y; a3.z += k * s3.z; a3.w += k * s3.w;
        }
    }

    // NCHW write: out[((b*16 + o) * H + y) * W + x]; per-o the warp is coalesced.
    size_t base = ((size_t)b * OO) * (HH * WW) + ((size_t)y * WW + x);
    const size_t plane = (size_t)HH * WW;
    float acc[16] = {a0.x, a0.y, a0.z, a0.w, a1.x, a1.y, a1.z, a1.w,
                     a2.x, a2.y, a2.z, a2.w, a3.x, a3.y, a3.z, a3.w};
    #pragma unroll
    for (int o = 0; o < 16; o++)
        out[base + (size_t)o * plane] = acc[o];
}

// ---------------------------------------------------------------------------
// Launch. Input order per metadata: node_feat, node_xy, hw(int64, unused),
// node_types(int32), w_obj, w_prior. Output: float32 [B,O,H,W].
// ---------------------------------------------------------------------------
extern "C" void kernel_launch(void* const* d_in, const int* in_sizes, int n_in,
                              void* d_out, int out_size) {
    const float* node_feat  = (const float*)d_in[0];
    const float* node_xy    = (const float*)d_in[1];
    // d_in[2] = hw (int64), shapes are compile-time constants here
    const int*   node_types = (const int*)d_in[3];
    const float* w_obj      = (const float*)d_in[4];
    const float* w_prior    = (const float*)d_in[5];
    float* out = (float*)d_out;

    // 1) zero the NHWC accumulation grid (8,388,608 float4)
    zero_kernel<<<(NPIX * 4 + 255) / 256, 256>>>();

    // 2) transform + scatter (800000 nodes)
    scatter_kernel<<<(NNODES + 255) / 256, 256>>>(node_feat, node_xy, node_types,
                                                  w_obj, w_prior);

    // 3) depthwise 3x3 conv + NCHW writeout (2,097,152 pixels)
    conv_kernel<<<(NPIX + 255) / 256, 256>>>(out);
}

// round 2
// speedup vs baseline: 1.0485x; 1.0485x over previous
#include <cuda_runtime.h>
#include <cstdint>

// Problem constants (fixed by the reference)
#define BB   8
#define KK   100000
#define CC   16
#define OO   16
#define HH   512
#define WW   512
#define NPIX_B (HH * WW)          // 262144 pixels per batch
#define ALPHA_PRIOR 1.0f

// ONE-BATCH scratch grid, [H, W, O] as float4 chunks (O=16 -> 4 float4/pixel).
// 512*512*4 float4 = 16.8 MB  ->  stays resident in the 126 MB L2 across batches.
__device__ float4 g_grid[(size_t)NPIX_B * 4];

// ---------------------------------------------------------------------------
// Kernel 1: zero the per-batch grid (1,048,576 float4)
// ---------------------------------------------------------------------------
__global__ __launch_bounds__(256) void zero_kernel() {
    size_t i = (size_t)blockIdx.x * 256 + threadIdx.x;
    g_grid[i] = make_float4(0.f, 0.f, 0.f, 0.f);
}

// ---------------------------------------------------------------------------
// Kernel 2: per-node channel transform + scatter-add (one batch of 100k nodes)
// ---------------------------------------------------------------------------
__device__ __forceinline__ float dot16(const float* w,
                                       float4 f0, float4 f1, float4 f2, float4 f3) {
    const float4* w4 = (const float4*)w;
    float4 w0 = w4[0], w1 = w4[1], w2 = w4[2], w3 = w4[3];
    return w0.x * f0.x + w0.y * f0.y + w0.z * f0.z + w0.w * f0.w
         + w1.x * f1.x + w1.y * f1.y + w1.z * f1.z + w1.w * f1.w
         + w2.x * f2.x + w2.y * f2.y + w2.z * f2.z + w2.w * f2.w
         + w3.x * f3.x + w3.y * f3.y + w3.z * f3.z + w3.w * f3.w;
}

__global__ __launch_bounds__(256) void scatter_kernel(
    const float* __restrict__ node_feat,   // [B,K,C]
    const float* __restrict__ node_xy,     // [B,K,2]
    const int*   __restrict__ node_types,  // [B,K]
    const float* __restrict__ w_obj,       // [O,C]
    const float* __restrict__ w_prior,     // [O,C]
    int b)
{
    __shared__ float sw[2][OO * CC];       // [type][o*16+c]
    int tid = threadIdx.x;
    if (tid < OO * CC) {
        sw[0][tid] = w_obj[tid];
        sw[1][tid] = ALPHA_PRIOR * w_prior[tid];
    }
    __syncthreads();

    int nl = blockIdx.x * 256 + tid;       // node index within batch
    if (nl >= KK) return;
    size_t n = (size_t)b * KK + nl;        // global node index

    const float4* f4 = (const float4*)(node_feat + n * CC);
    float4 f0 = f4[0], f1 = f4[1], f2 = f4[2], f3 = f4[3];

    float x = node_xy[2 * n + 0];
    float y = node_xy[2 * n + 1];
    int   t = node_types[n] & 1;

    // jnp.round == round-half-to-even == rintf; clip to [0, 511]
    int ix = (int)fminf(fmaxf(rintf(x), 0.f), (float)(WW - 1));
    int iy = (int)fminf(fmaxf(rintf(y), 0.f), (float)(HH - 1));

    const float* wbase = sw[t];
    float4* dst = &g_grid[((size_t)iy * WW + ix) * 4];

    #pragma unroll
    for (int g = 0; g < 4; g++) {
        float4 v;
        v.x = dot16(wbase + (g * 4 + 0) * CC, f0, f1, f2, f3);
        v.y = dot16(wbase + (g * 4 + 1) * CC, f0, f1, f2, f3);
        v.z = dot16(wbase + (g * 4 + 2) * CC, f0, f1, f2, f3);
        v.w = dot16(wbase + (g * 4 + 3) * CC, f0, f1, f2, f3);
        asm volatile("red.global.add.v4.f32 [%0], {%1, %2, %3, %4};"
                     :: "l"(dst + g), "f"(v.x), "f"(v.y), "f"(v.z), "f"(v.w)
                     : "memory");
    }
}

// ---------------------------------------------------------------------------
// Kernel 3: depthwise 3x3 conv over the batch grid, NCHW output writeout.
// Each thread: one x column, a strip of 4 consecutive y rows.
// Row-combo reuse: 6 rows read per 4 rows produced (1.5x amplification).
// Per input row r:  u = 0.075*(l+r) + 0.125*c   (contribution to y = r -/+ 1)
//                   v = 0.125*(l+r) + 0.300*c   (contribution to y = r)
// ---------------------------------------------------------------------------
__global__ __launch_bounds__(128) void conv_kernel(float* __restrict__ out, int b) {
    int x  = blockIdx.x * 128 + threadIdx.x;   // 0..511
    int y0 = blockIdx.y * 4;                   // strip start

    float acc[4][16];
    #pragma unroll
    for (int j = 0; j < 4; j++)
        #pragma unroll
        for (int i = 0; i < 16; i++) acc[j][i] = 0.f;

    const float4 z4 = make_float4(0.f, 0.f, 0.f, 0.f);

    #pragma unroll
    for (int r = 0; r < 6; r++) {
        int yy = y0 - 1 + r;
        if ((unsigned)yy >= HH) continue;      // y zero-pad

        const float4* row = &g_grid[(size_t)yy * (WW * 4)];
        float4 c[4], l[4], rr[4];
        #pragma unroll
        for (int g = 0; g < 4; g++) {
            c[g]  = __ldg(&row[(size_t)x * 4 + g]);
            l[g]  = (x > 0)      ? __ldg(&row[(size_t)(x - 1) * 4 + g]) : z4;
            rr[g] = (x < WW - 1) ? __ldg(&row[(size_t)(x + 1) * 4 + g]) : z4;
        }

        float u[16], v[16];
        #pragma unroll
        for (int g = 0; g < 4; g++) {
            float sx = l[g].x + rr[g].x, sy = l[g].y + rr[g].y;
            float sz = l[g].z + rr[g].z, sw_ = l[g].w + rr[g].w;
            u[g*4+0] = 0.075f * sx  + 0.125f * c[g].x;
            u[g*4+1] = 0.075f * sy  + 0.125f * c[g].y;
            u[g*4+2] = 0.075f * sz  + 0.125f * c[g].z;
            u[g*4+3] = 0.075f * sw_ + 0.125f * c[g].w;
            v[g*4+0] = 0.125f * sx  + 0.300f * c[g].x;
            v[g*4+1] = 0.125f * sy  + 0.300f * c[g].y;
            v[g*4+2] = 0.125f * sz  + 0.300f * c[g].z;
            v[g*4+3] = 0.125f * sw_ + 0.300f * c[g].w;
        }

        // row yy contributes: u to outputs yy-1 and yy+1, v to output yy
        #pragma unroll
        for (int j = 0; j < 4; j++) {
            int oy = y0 + j;                   // (compile-time relation: oy = y0 + j, yy = y0 - 1 + r)
            int d  = (r - 1) - j;              // yy - oy
            if (d == 0) {
                #pragma unroll
                for (int i = 0; i < 16; i++) acc[j][i] += v[i];
            } else if (d == 1 || d == -1) {
                #pragma unroll
                for (int i = 0; i < 16; i++) acc[j][i] += u[i];
            }
            (void)oy;
        }
    }

    // NCHW writeout: out[((b*16 + o) * H + y) * W + x]
    const size_t plane = (size_t)HH * WW;
    size_t base = (size_t)b * OO * plane + (size_t)y0 * WW + x;
    #pragma unroll
    for (int o = 0; o < 16; o++)
        #pragma unroll
        for (int j = 0; j < 4; j++)
            out[base + (size_t)o * plane + (size_t)j * WW] = acc[j][o];
}

// ---------------------------------------------------------------------------
// Launch: 8 sequential batches through the L2-resident scratch grid.
// Inputs: node_feat, node_xy, hw(int64, unused), node_types, w_obj, w_prior.
// ---------------------------------------------------------------------------
extern "C" void kernel_launch(void* const* d_in, const int* in_sizes, int n_in,
                              void* d_out, int out_size) {
    const float* node_feat  = (const float*)d_in[0];
    const float* node_xy    = (const float*)d_in[1];
    const int*   node_types = (const int*)d_in[3];
    const float* w_obj      = (const float*)d_in[4];
    const float* w_prior    = (const float*)d_in[5];
    float* out = (float*)d_out;

    dim3 conv_grid(WW / 128, HH / 4);          // (4, 128) = 512 blocks

    for (int b = 0; b < BB; b++) {
        zero_kernel<<<(NPIX_B * 4) / 256, 256>>>();
        scatter_kernel<<<(KK + 255) / 256, 256>>>(node_feat, node_xy, node_types,
                                                  w_obj, w_prior, b);
        conv_kernel<<<conv_grid, 128>>>(out, b);
    }
}

// round 3
// speedup vs baseline: 1.4403x; 1.3736x over previous
#include <cuda_runtime.h>
#include <cstdint>

// Problem constants (fixed by the reference)
#define BB   8
#define KK   100000
#define CC   16
#define OO   16
#define HH   512
#define WW   512
#define NPIX_B (HH * WW)          // 262144 pixels per batch
#define ALPHA_PRIOR 1.0f
#define NCHAIN 4                  // parallel batch pipelines
#define GRID_F4 ((size_t)NPIX_B * 4)   // float4 elems per scratch grid

// NCHAIN one-batch scratch grids, [H, W, O] as float4 chunks.
// 4 * 16.8 MB = 67 MB -> L2-resident working set while streaming output.
__device__ float4 g_grid[NCHAIN][GRID_F4];

// ---------------------------------------------------------------------------
// Kernel 1: zero one scratch grid (1,048,576 float4)
// ---------------------------------------------------------------------------
__global__ __launch_bounds__(256) void zero_kernel(int buf) {
    size_t i = (size_t)blockIdx.x * 256 + threadIdx.x;
    g_grid[buf][i] = make_float4(0.f, 0.f, 0.f, 0.f);
}

// ---------------------------------------------------------------------------
// Kernel 2: per-node channel transform + scatter-add (one batch of 100k nodes)
// ---------------------------------------------------------------------------
__device__ __forceinline__ float dot16(const float* w,
                                       float4 f0, float4 f1, float4 f2, float4 f3) {
    const float4* w4 = (const float4*)w;
    float4 w0 = w4[0], w1 = w4[1], w2 = w4[2], w3 = w4[3];
    return w0.x * f0.x + w0.y * f0.y + w0.z * f0.z + w0.w * f0.w
         + w1.x * f1.x + w1.y * f1.y + w1.z * f1.z + w1.w * f1.w
         + w2.x * f2.x + w2.y * f2.y + w2.z * f2.z + w2.w * f2.w
         + w3.x * f3.x + w3.y * f3.y + w3.z * f3.z + w3.w * f3.w;
}

__global__ __launch_bounds__(256) void scatter_kernel(
    const float* __restrict__ node_feat,   // [B,K,C]
    const float* __restrict__ node_xy,     // [B,K,2]
    const int*   __restrict__ node_types,  // [B,K]
    const float* __restrict__ w_obj,       // [O,C]
    const float* __restrict__ w_prior,     // [O,C]
    int b, int buf)
{
    __shared__ float sw[2][OO * CC];       // [type][o*16+c]
    int tid = threadIdx.x;
    if (tid < OO * CC) {
        sw[0][tid] = w_obj[tid];
        sw[1][tid] = ALPHA_PRIOR * w_prior[tid];
    }
    __syncthreads();

    int nl = blockIdx.x * 256 + tid;       // node index within batch
    if (nl >= KK) return;
    size_t n = (size_t)b * KK + nl;        // global node index

    const float4* f4 = (const float4*)(node_feat + n * CC);
    float4 f0 = f4[0], f1 = f4[1], f2 = f4[2], f3 = f4[3];

    float x = node_xy[2 * n + 0];
    float y = node_xy[2 * n + 1];
    int   t = node_types[n] & 1;

    // jnp.round == round-half-to-even == rintf; clip to [0, 511]
    int ix = (int)fminf(fmaxf(rintf(x), 0.f), (float)(WW - 1));
    int iy = (int)fminf(fmaxf(rintf(y), 0.f), (float)(HH - 1));

    const float* wbase = sw[t];
    float4* dst = &g_grid[buf][((size_t)iy * WW + ix) * 4];

    #pragma unroll
    for (int g = 0; g < 4; g++) {
        float4 v;
        v.x = dot16(wbase + (g * 4 + 0) * CC, f0, f1, f2, f3);
        v.y = dot16(wbase + (g * 4 + 1) * CC, f0, f1, f2, f3);
        v.z = dot16(wbase + (g * 4 + 2) * CC, f0, f1, f2, f3);
        v.w = dot16(wbase + (g * 4 + 3) * CC, f0, f1, f2, f3);
        asm volatile("red.global.add.v4.f32 [%0], {%1, %2, %3, %4};"
                     :: "l"(dst + g), "f"(v.x), "f"(v.y), "f"(v.z), "f"(v.w)
                     : "memory");
    }
}

// ---------------------------------------------------------------------------
// Kernel 3: depthwise 3x3 conv over the batch grid, NCHW output writeout.
// Each thread: one x column, a strip of 4 consecutive y rows (6 rows read).
// ---------------------------------------------------------------------------
__global__ __launch_bounds__(128) void conv_kernel(float* __restrict__ out,
                                                   int b, int buf) {
    int x  = blockIdx.x * 128 + threadIdx.x;   // 0..511
    int y0 = blockIdx.y * 4;                   // strip start

    float acc[4][16];
    #pragma unroll
    for (int j = 0; j < 4; j++)
        #pragma unroll
        for (int i = 0; i < 16; i++) acc[j][i] = 0.f;

    const float4 z4 = make_float4(0.f, 0.f, 0.f, 0.f);
    const float4* grid = g_grid[buf];

    #pragma unroll
    for (int r = 0; r < 6; r++) {
        int yy = y0 - 1 + r;
        if ((unsigned)yy >= HH) continue;      // y zero-pad

        const float4* row = &grid[(size_t)yy * (WW * 4)];
        float4 c[4], l[4], rr[4];
        #pragma unroll
        for (int g = 0; g < 4; g++) {
            c[g]  = __ldg(&row[(size_t)x * 4 + g]);
            l[g]  = (x > 0)      ? __ldg(&row[(size_t)(x - 1) * 4 + g]) : z4;
            rr[g] = (x < WW - 1) ? __ldg(&row[(size_t)(x + 1) * 4 + g]) : z4;
        }

        float u[16], v[16];
        #pragma unroll
        for (int g = 0; g < 4; g++) {
            float sx = l[g].x + rr[g].x, sy = l[g].y + rr[g].y;
            float sz = l[g].z + rr[g].z, sw_ = l[g].w + rr[g].w;
            u[g*4+0] = 0.075f * sx  + 0.125f * c[g].x;
            u[g*4+1] = 0.075f * sy  + 0.125f * c[g].y;
            u[g*4+2] = 0.075f * sz  + 0.125f * c[g].z;
            u[g*4+3] = 0.075f * sw_ + 0.125f * c[g].w;
            v[g*4+0] = 0.125f * sx  + 0.300f * c[g].x;
            v[g*4+1] = 0.125f * sy  + 0.300f * c[g].y;
            v[g*4+2] = 0.125f * sz  + 0.300f * c[g].z;
            v[g*4+3] = 0.125f * sw_ + 0.300f * c[g].w;
        }

        #pragma unroll
        for (int j = 0; j < 4; j++) {
            int d = (r - 1) - j;               // input row offset from output row
            if (d == 0) {
                #pragma unroll
                for (int i = 0; i < 16; i++) acc[j][i] += v[i];
            } else if (d == 1 || d == -1) {
                #pragma unroll
                for (int i = 0; i < 16; i++) acc[j][i] += u[i];
            }
        }
    }

    // NCHW writeout: out[((b*16 + o) * H + y) * W + x]
    const size_t plane = (size_t)HH * WW;
    size_t base = (size_t)b * OO * plane + (size_t)y0 * WW + x;
    #pragma unroll
    for (int o = 0; o < 16; o++)
        #pragma unroll
        for (int j = 0; j < 4; j++)
            out[base + (size_t)o * plane + (size_t)j * WW] = acc[j][o];
}

// ---------------------------------------------------------------------------
// Launch: 4 parallel chains (capture-stream fork/join), 2 batches per chain,
// each chain owning one L2-resident scratch grid.
// Streams/events created once on the first (uncaptured) correctness call.
// ---------------------------------------------------------------------------
extern "C" void kernel_launch(void* const* d_in, const int* in_sizes, int n_in,
                              void* d_out, int out_size) {
    const float* node_feat  = (const float*)d_in[0];
    const float* node_xy    = (const float*)d_in[1];
    const int*   node_types = (const int*)d_in[3];
    const float* w_obj      = (const float*)d_in[4];
    const float* w_prior    = (const float*)d_in[5];
    float* out = (float*)d_out;

    static cudaStream_t side[NCHAIN - 1];
    static cudaEvent_t  fork_ev, join_ev[NCHAIN - 1];
    static bool init = false;
    if (!init) {
        for (int i = 0; i < NCHAIN - 1; i++) {
            cudaStreamCreateWithFlags(&side[i], cudaStreamNonBlocking);
            cudaEventCreateWithFlags(&join_ev[i], cudaEventDisableTiming);
        }
        cudaEventCreateWithFlags(&fork_ev, cudaEventDisableTiming);
        init = true;
    }

    dim3 conv_grid(WW / 128, HH / 4);          // 512 blocks

    // Fork: side streams join the capture dependency graph.
    cudaEventRecord(fork_ev, 0);
    for (int i = 0; i < NCHAIN - 1; i++)
        cudaStreamWaitEvent(side[i], fork_ev, 0);

    for (int c = 0; c < NCHAIN; c++) {
        cudaStream_t s = (c == 0) ? (cudaStream_t)0 : side[c - 1];
        for (int k = 0; k < BB / NCHAIN; k++) {
            int b = c + k * NCHAIN;            // batches {c, c+4}
            zero_kernel<<<(int)(GRID_F4 / 256), 256, 0, s>>>(c);
            scatter_kernel<<<(KK + 255) / 256, 256, 0, s>>>(
                node_feat, node_xy, node_types, w_obj, w_prior, b, c);
            conv_kernel<<<conv_grid, 128, 0, s>>>(out, b, c);
        }
    }

    // Join: capture stream waits on all side chains.
    for (int i = 0; i < NCHAIN - 1; i++) {
        cudaEventRecord(join_ev[i], side[i]);
        cudaStreamWaitEvent((cudaStream_t)0, join_ev[i], 0);
    }
}